// round 3
// baseline (speedup 1.0000x reference)
#include <cuda_runtime.h>
#include <cuda_bf16.h>
#include <cstddef>

#define NN 50000
#define NE 600000
#define NF 128
#define NG 500

// ---------------- device scratch (static, no allocation) ----------------
__device__ float g_bufA[NN * NF];
__device__ float g_bufB[NN * NF];
__device__ float g_lin[NN * NF];   // x @ Wl
__device__ float g_root[NN * NF];  // x @ Wr
__device__ int   g_deg[NN];
__device__ int   g_off[NN + 1];
__device__ int   g_cur[NN];
__device__ int   g_esrc[NE];
__device__ float g_gsum[NG];
__device__ int   g_gcnt[NG];

// ---------------- CSR build ----------------
__global__ void zero_kernel() {
    int i = blockIdx.x * blockDim.x + threadIdx.x;
    if (i < NN) g_deg[i] = 0;
    if (i < NG) { g_gcnt[i] = 0; g_gsum[i] = 0.0f; }
}

__global__ void hist_kernel(const int* __restrict__ ei,
                            const int* __restrict__ batch) {
    int i = blockIdx.x * blockDim.x + threadIdx.x;
    if (i < NE) {
        int d = ei[NE + i];
        if (d >= 0 && d < NN) atomicAdd(&g_deg[d], 1);
    }
    if (i < NN) {
        int b = batch[i];
        if (b >= 0 && b < NG) atomicAdd(&g_gcnt[b], 1);
    }
}

// single-block exclusive scan over g_deg -> g_off (and g_cur)
__global__ void scan_kernel() {
    __shared__ int warpsum[32];
    __shared__ int s_carry;
    int tid = threadIdx.x, lane = tid & 31, wid = tid >> 5;
    if (tid == 0) s_carry = 0;
    __syncthreads();
    for (int base = 0; base < NN; base += 1024) {
        int i = base + tid;
        int v = (i < NN) ? g_deg[i] : 0;
        int x = v;
        #pragma unroll
        for (int o = 1; o < 32; o <<= 1) {
            int t = __shfl_up_sync(0xFFFFFFFFu, x, o);
            if (lane >= o) x += t;
        }
        if (lane == 31) warpsum[wid] = x;
        __syncthreads();
        if (wid == 0) {
            int y = warpsum[lane];
            #pragma unroll
            for (int o = 1; o < 32; o <<= 1) {
                int t = __shfl_up_sync(0xFFFFFFFFu, y, o);
                if (lane >= o) y += t;
            }
            warpsum[lane] = y;
        }
        __syncthreads();
        int wprefix = (wid > 0) ? warpsum[wid - 1] : 0;
        int excl = x - v + wprefix + s_carry;
        if (i < NN) { g_off[i] = excl; g_cur[i] = excl; }
        __syncthreads();
        if (tid == 0) s_carry += warpsum[31];
        __syncthreads();
    }
    if (threadIdx.x == 0) g_off[NN] = NE;
}

__global__ void scatter_kernel(const int* __restrict__ ei) {
    int i = blockIdx.x * blockDim.x + threadIdx.x;
    if (i < NE) {
        int s = ei[i];
        int d = ei[NE + i];
        if (d >= 0 && d < NN) {
            int p = atomicAdd(&g_cur[d], 1);
            g_esrc[p] = s;
        }
    }
}

// ---------------- fused dual GEMM: lin = src@Wl, root = src@Wr ----------------
// src selected by layer: 0 -> external X, 1 -> g_bufA, 2 -> g_bufB
// BM=64, BN=128, BK=64, 256 threads, thread tile 8x4
__global__ __launch_bounds__(256) void gemm2_kernel(int layer,
                                                    const float* __restrict__ X,
                                                    const float* __restrict__ Wl,
                                                    const float* __restrict__ Wr) {
    const float* src = (layer == 0) ? X : ((layer == 1) ? g_bufA : g_bufB);
    const float* W  = blockIdx.y ? Wr : Wl;
    float* out      = blockIdx.y ? g_root : g_lin;
    __shared__ float As[64][64];
    __shared__ float Bs[64][128];
    int tid = threadIdx.x;
    int tx = tid & 31, ty = tid >> 5;
    int row0 = blockIdx.x * 64;
    float acc[8][4];
    #pragma unroll
    for (int i = 0; i < 8; i++)
        #pragma unroll
        for (int j = 0; j < 4; j++) acc[i][j] = 0.0f;

    for (int kk = 0; kk < NF; kk += 64) {
        #pragma unroll
        for (int i = 0; i < 4; i++) {
            int slot = tid + 256 * i;          // 0..1023 float4 slots
            int r = slot >> 4;
            int c = (slot & 15) << 2;
            float4 v = make_float4(0.f, 0.f, 0.f, 0.f);
            if (row0 + r < NN)
                v = *(const float4*)(src + (size_t)(row0 + r) * NF + kk + c);
            *(float4*)&As[r][c] = v;
        }
        #pragma unroll
        for (int i = 0; i < 8; i++) {
            int slot = tid + 256 * i;          // 0..2047 float4 slots
            int r = slot >> 5;
            int c = (slot & 31) << 2;
            *(float4*)&Bs[r][c] = *(const float4*)(W + (size_t)(kk + r) * NF + c);
        }
        __syncthreads();
        #pragma unroll 16
        for (int k = 0; k < 64; k++) {
            float4 b = *(float4*)&Bs[k][tx << 2];
            #pragma unroll
            for (int i = 0; i < 8; i++) {
                float a = As[ty * 8 + i][k];
                acc[i][0] += a * b.x;
                acc[i][1] += a * b.y;
                acc[i][2] += a * b.z;
                acc[i][3] += a * b.w;
            }
        }
        __syncthreads();
    }
    #pragma unroll
    for (int i = 0; i < 8; i++) {
        int r = row0 + ty * 8 + i;
        if (r < NN)
            *(float4*)(out + (size_t)r * NF + (tx << 2)) =
                make_float4(acc[i][0], acc[i][1], acc[i][2], acc[i][3]);
    }
}

// ---------------- aggregation: dst = relu(mean_in(lin) + bl + root) ----------------
// dst selected by layer: 0 -> g_bufA, 1 -> g_bufB, 2 -> g_bufA
__global__ void agg_kernel(int layer, const float* __restrict__ bl) {
    float* xout = (layer == 1) ? g_bufB : g_bufA;
    int n = blockIdx.x;
    int f = threadIdx.x;
    int beg = g_off[n], end = g_off[n + 1];
    float acc = 0.0f;
    int e = beg;
    for (; e + 4 <= end; e += 4) {
        int s0 = g_esrc[e + 0];
        int s1 = g_esrc[e + 1];
        int s2 = g_esrc[e + 2];
        int s3 = g_esrc[e + 3];
        acc += g_lin[(size_t)s0 * NF + f];
        acc += g_lin[(size_t)s1 * NF + f];
        acc += g_lin[(size_t)s2 * NF + f];
        acc += g_lin[(size_t)s3 * NF + f];
    }
    for (; e < end; e++)
        acc += g_lin[(size_t)g_esrc[e] * NF + f];
    int d = end - beg;
    float m = (d > 0) ? acc / (float)d : 0.0f;
    float v = m + bl[f] + g_root[(size_t)n * NF + f];
    xout[(size_t)n * NF + f] = fmaxf(v, 0.0f);
}

// ---------------- head: per-node dot with W_out, pooled per graph ----------------
// reads layer-2 output (g_bufA)
__global__ void final_dot_kernel(const float* __restrict__ Wout,
                                 const int* __restrict__ batch) {
    int warp = (blockIdx.x * blockDim.x + threadIdx.x) >> 5;
    int lane = threadIdx.x & 31;
    if (warp >= NN) return;
    float4 a = *(const float4*)(g_bufA + (size_t)warp * NF + lane * 4);
    float4 w = *(const float4*)(Wout + lane * 4);
    float s = a.x * w.x + a.y * w.y + a.z * w.z + a.w * w.w;
    #pragma unroll
    for (int o = 16; o; o >>= 1) s += __shfl_xor_sync(0xFFFFFFFFu, s, o);
    if (lane == 0) {
        int b = batch[warp];
        if (b >= 0 && b < NG) atomicAdd(&g_gsum[b], s);
    }
}

__global__ void final_out_kernel(float* __restrict__ out, const float* __restrict__ b_out) {
    int g = blockIdx.x * blockDim.x + threadIdx.x;
    if (g < NG) {
        float c = fmaxf((float)g_gcnt[g], 1.0f);
        out[g] = g_gsum[g] / c + b_out[0];
    }
}

// ---------------- host launcher ----------------
extern "C" void kernel_launch(void* const* d_in, const int* in_sizes, int n_in,
                              void* d_out, int out_size) {
    const float* x     = (const float*)d_in[0];
    const int*   ei    = (const int*)d_in[1];
    const int*   batch = (const int*)d_in[2];
    const float* Wl[3] = { (const float*)d_in[3], (const float*)d_in[6], (const float*)d_in[9]  };
    const float* bl[3] = { (const float*)d_in[4], (const float*)d_in[7], (const float*)d_in[10] };
    const float* Wr[3] = { (const float*)d_in[5], (const float*)d_in[8], (const float*)d_in[11] };
    const float* W_out = (const float*)d_in[12];
    const float* b_out = (const float*)d_in[13];
    float* out = (float*)d_out;

    // CSR build
    zero_kernel<<<(NN + 255) / 256, 256>>>();
    hist_kernel<<<(NE + 255) / 256, 256>>>(ei, batch);
    scan_kernel<<<1, 1024>>>();
    scatter_kernel<<<(NE + 255) / 256, 256>>>(ei);

    // 3 SAGE layers
    dim3 ggrid((NN + 63) / 64, 2);
    for (int l = 0; l < 3; l++) {
        gemm2_kernel<<<ggrid, 256>>>(l, x, Wl[l], Wr[l]);
        agg_kernel<<<NN, NF>>>(l, bl[l]);
    }

    // head: dot + pooled mean + bias
    final_dot_kernel<<<(NN * 32 + 255) / 256, 256>>>(W_out, batch);
    final_out_kernel<<<(NG + 255) / 256, 256>>>(out, b_out);
}

// round 5
// speedup vs baseline: 1.2934x; 1.2934x over previous
#include <cuda_runtime.h>
#include <cuda_bf16.h>
#include <cstdint>
#include <cstddef>

#define NN 50000
#define NE 600000
#define NF 128
#define NG 500

// ---------------- device scratch (static, no allocation) ----------------
__device__ float g_bufA[NN * NF];
__device__ float g_bufB[NN * NF];
__device__ float g_lin[NN * NF];   // x @ Wl
__device__ float g_root[NN * NF];  // x @ Wr
__device__ int   g_deg[NN];
__device__ int   g_off[NN + 1];
__device__ int   g_cur[NN];
__device__ int   g_esrc[NE];
__device__ float g_gsum[NG];
__device__ int   g_gcnt[NG];

// ---------------- CSR build ----------------
__global__ void zero_kernel() {
    int i = blockIdx.x * blockDim.x + threadIdx.x;
    if (i < NN) g_deg[i] = 0;
    if (i < NG) { g_gcnt[i] = 0; g_gsum[i] = 0.0f; }
}

__global__ void hist_kernel(const int* __restrict__ ei, const int* __restrict__ batch) {
    int i = blockIdx.x * blockDim.x + threadIdx.x;
    if (i < NE) {
        int d = ei[NE + i];
        if (d >= 0 && d < NN) atomicAdd(&g_deg[d], 1);
    }
    if (i < NN) {
        int b = batch[i];
        if (b >= 0 && b < NG) atomicAdd(&g_gcnt[b], 1);
    }
}

__global__ void scan_kernel() {
    __shared__ int warpsum[32];
    __shared__ int s_carry;
    int tid = threadIdx.x, lane = tid & 31, wid = tid >> 5;
    if (tid == 0) s_carry = 0;
    __syncthreads();
    for (int base = 0; base < NN; base += 1024) {
        int i = base + tid;
        int v = (i < NN) ? g_deg[i] : 0;
        int x = v;
        #pragma unroll
        for (int o = 1; o < 32; o <<= 1) {
            int t = __shfl_up_sync(0xFFFFFFFFu, x, o);
            if (lane >= o) x += t;
        }
        if (lane == 31) warpsum[wid] = x;
        __syncthreads();
        if (wid == 0) {
            int y = warpsum[lane];
            #pragma unroll
            for (int o = 1; o < 32; o <<= 1) {
                int t = __shfl_up_sync(0xFFFFFFFFu, y, o);
                if (lane >= o) y += t;
            }
            warpsum[lane] = y;
        }
        __syncthreads();
        int wprefix = (wid > 0) ? warpsum[wid - 1] : 0;
        int excl = x - v + wprefix + s_carry;
        if (i < NN) { g_off[i] = excl; g_cur[i] = excl; }
        __syncthreads();
        if (tid == 0) s_carry += warpsum[31];
        __syncthreads();
    }
    if (threadIdx.x == 0) g_off[NN] = NE;
}

__global__ void scatter_kernel(const int* __restrict__ ei) {
    int i = blockIdx.x * blockDim.x + threadIdx.x;
    if (i < NE) {
        int s = ei[i];
        int d = ei[NE + i];
        if (d >= 0 && d < NN) {
            int p = atomicAdd(&g_cur[d], 1);
            g_esrc[p] = s;
        }
    }
}

// ---------------- tensor-core GEMM via mma.sync tf32 (3xTF32 for fp32 accuracy) ----
// M-tile 64, N=128 full. blockIdx.y: 0 -> out=g_lin (W=Wl), 1 -> out=g_root (W=Wr)
// SMEM float strides: A=132, B=136 (bank-conflict-free fragment loads)
#define MT 64
#define SA_STRIDE 132
#define SB_STRIDE 136
#define SA_FLOATS (MT * SA_STRIDE)          // 8448
#define SB_FLOATS (128 * SB_STRIDE)         // 17408
#define GEMM_SMEM_BYTES ((2 * SA_FLOATS + 2 * SB_FLOATS) * 4)   // 206848

__device__ __forceinline__ uint32_t f2tf32(float f) {
    uint32_t r;
    asm("cvt.rna.tf32.f32 %0, %1;" : "=r"(r) : "f"(f));
    return r;
}

__device__ __forceinline__ void mma_tf32(float* c, const uint32_t* a, const uint32_t* b) {
    asm volatile(
        "mma.sync.aligned.m16n8k8.row.col.f32.tf32.tf32.f32 "
        "{%0,%1,%2,%3}, {%4,%5,%6,%7}, {%8,%9}, {%0,%1,%2,%3};"
        : "+f"(c[0]), "+f"(c[1]), "+f"(c[2]), "+f"(c[3])
        : "r"(a[0]), "r"(a[1]), "r"(a[2]), "r"(a[3]), "r"(b[0]), "r"(b[1]));
}

__global__ __launch_bounds__(256) void gemm2_kernel(int layer,
                                                    const float* __restrict__ X,
                                                    const float* __restrict__ Wl,
                                                    const float* __restrict__ Wr) {
    extern __shared__ float smem[];
    float* As_hi = smem;
    float* As_lo = smem + SA_FLOATS;
    float* Bs_hi = smem + 2 * SA_FLOATS;
    float* Bs_lo = smem + 2 * SA_FLOATS + SB_FLOATS;

    const float* src = (layer == 0) ? X : ((layer == 1) ? g_bufA : g_bufB);
    const float* W   = blockIdx.y ? Wr : Wl;
    float* outp      = blockIdx.y ? g_root : g_lin;

    int tid = threadIdx.x, lane = tid & 31, wid = tid >> 5;
    int row0 = blockIdx.x * MT;

    // Load A tile (64 x 128) with tf32 hi/lo split
    #pragma unroll
    for (int i = 0; i < 8; i++) {
        int slot = tid + i * 256;           // 0..2047 float4 slots
        int r = slot >> 5;
        int c = (slot & 31) << 2;
        float4 v = make_float4(0.f, 0.f, 0.f, 0.f);
        if (row0 + r < NN) v = *(const float4*)(src + (size_t)(row0 + r) * NF + c);
        float4 hi, lo;
        hi.x = __uint_as_float(f2tf32(v.x)); lo.x = __uint_as_float(f2tf32(v.x - hi.x));
        hi.y = __uint_as_float(f2tf32(v.y)); lo.y = __uint_as_float(f2tf32(v.y - hi.y));
        hi.z = __uint_as_float(f2tf32(v.z)); lo.z = __uint_as_float(f2tf32(v.z - hi.z));
        hi.w = __uint_as_float(f2tf32(v.w)); lo.w = __uint_as_float(f2tf32(v.w - hi.w));
        *(float4*)(As_hi + r * SA_STRIDE + c) = hi;
        *(float4*)(As_lo + r * SA_STRIDE + c) = lo;
    }
    // Load B tile (128 x 128): Bs[k][n] = W[k*NF + n]
    #pragma unroll
    for (int i = 0; i < 16; i++) {
        int slot = tid + i * 256;           // 0..4095 float4 slots
        int k = slot >> 5;
        int n = (slot & 31) << 2;
        float4 v = *(const float4*)(W + (size_t)k * NF + n);
        float4 hi, lo;
        hi.x = __uint_as_float(f2tf32(v.x)); lo.x = __uint_as_float(f2tf32(v.x - hi.x));
        hi.y = __uint_as_float(f2tf32(v.y)); lo.y = __uint_as_float(f2tf32(v.y - hi.y));
        hi.z = __uint_as_float(f2tf32(v.z)); lo.z = __uint_as_float(f2tf32(v.z - hi.z));
        hi.w = __uint_as_float(f2tf32(v.w)); lo.w = __uint_as_float(f2tf32(v.w - hi.w));
        *(float4*)(Bs_hi + k * SB_STRIDE + n) = hi;
        *(float4*)(Bs_lo + k * SB_STRIDE + n) = lo;
    }
    __syncthreads();

    // warp tiling: 2 (M) x 4 (N) warps; warp tile 32x32
    int warp_m = wid >> 2;
    int warp_n = wid & 3;
    int m_base = warp_m * 32;
    int n_base = warp_n * 32;
    int frow = lane >> 2;    // fragment row group
    int fcol = lane & 3;     // fragment k group

    float c[2][4][4];
    #pragma unroll
    for (int mi = 0; mi < 2; mi++)
        #pragma unroll
        for (int ni = 0; ni < 4; ni++)
            #pragma unroll
            for (int j = 0; j < 4; j++) c[mi][ni][j] = 0.0f;

    #pragma unroll
    for (int ks = 0; ks < 16; ks++) {
        int k0 = ks * 8;
        uint32_t a_hi[2][4], a_lo[2][4];
        #pragma unroll
        for (int mi = 0; mi < 2; mi++) {
            int rb = m_base + mi * 16;
            a_hi[mi][0] = __float_as_uint(As_hi[(rb + frow) * SA_STRIDE + k0 + fcol]);
            a_hi[mi][1] = __float_as_uint(As_hi[(rb + frow + 8) * SA_STRIDE + k0 + fcol]);
            a_hi[mi][2] = __float_as_uint(As_hi[(rb + frow) * SA_STRIDE + k0 + fcol + 4]);
            a_hi[mi][3] = __float_as_uint(As_hi[(rb + frow + 8) * SA_STRIDE + k0 + fcol + 4]);
            a_lo[mi][0] = __float_as_uint(As_lo[(rb + frow) * SA_STRIDE + k0 + fcol]);
            a_lo[mi][1] = __float_as_uint(As_lo[(rb + frow + 8) * SA_STRIDE + k0 + fcol]);
            a_lo[mi][2] = __float_as_uint(As_lo[(rb + frow) * SA_STRIDE + k0 + fcol + 4]);
            a_lo[mi][3] = __float_as_uint(As_lo[(rb + frow + 8) * SA_STRIDE + k0 + fcol + 4]);
        }
        uint32_t b_hi[4][2], b_lo[4][2];
        #pragma unroll
        for (int ni = 0; ni < 4; ni++) {
            int n = n_base + ni * 8 + frow;
            int k = k0 + fcol;
            b_hi[ni][0] = __float_as_uint(Bs_hi[k * SB_STRIDE + n]);
            b_hi[ni][1] = __float_as_uint(Bs_hi[(k + 4) * SB_STRIDE + n]);
            b_lo[ni][0] = __float_as_uint(Bs_lo[k * SB_STRIDE + n]);
            b_lo[ni][1] = __float_as_uint(Bs_lo[(k + 4) * SB_STRIDE + n]);
        }
        #pragma unroll
        for (int mi = 0; mi < 2; mi++)
            #pragma unroll
            for (int ni = 0; ni < 4; ni++) {
                mma_tf32(c[mi][ni], a_hi[mi], b_hi[ni]);
                mma_tf32(c[mi][ni], a_hi[mi], b_lo[ni]);
                mma_tf32(c[mi][ni], a_lo[mi], b_hi[ni]);
            }
    }

    // epilogue
    #pragma unroll
    for (int mi = 0; mi < 2; mi++) {
        int r0 = row0 + m_base + mi * 16 + frow;
        int r1 = r0 + 8;
        #pragma unroll
        for (int ni = 0; ni < 4; ni++) {
            int col = n_base + ni * 8 + 2 * fcol;
            if (r0 < NN)
                *(float2*)(outp + (size_t)r0 * NF + col) = make_float2(c[mi][ni][0], c[mi][ni][1]);
            if (r1 < NN)
                *(float2*)(outp + (size_t)r1 * NF + col) = make_float2(c[mi][ni][2], c[mi][ni][3]);
        }
    }
}

// ---------------- aggregation: dst = relu(mean_in(lin) + bl + root) ----------------
// 128 threads: lane owns float4 feature chunk, 4 warps split the edge list
__global__ __launch_bounds__(128) void agg_kernel(int layer, const float* __restrict__ bl) {
    float* xout = (layer == 1) ? g_bufB : g_bufA;
    __shared__ float4 red[4][32];
    int n = blockIdx.x;
    int tid = threadIdx.x, lane = tid & 31, wid = tid >> 5;
    int beg = g_off[n], end = g_off[n + 1];
    float4 acc = make_float4(0.f, 0.f, 0.f, 0.f);
    for (int e = beg + wid; e < end; e += 4) {
        int s = g_esrc[e];
        float4 v = *(const float4*)(g_lin + (size_t)s * NF + lane * 4);
        acc.x += v.x; acc.y += v.y; acc.z += v.z; acc.w += v.w;
    }
    red[wid][lane] = acc;
    __syncthreads();
    if (wid == 0) {
        float4 a = red[0][lane], b1 = red[1][lane], c = red[2][lane], d4 = red[3][lane];
        a.x += b1.x + c.x + d4.x;
        a.y += b1.y + c.y + d4.y;
        a.z += b1.z + c.z + d4.z;
        a.w += b1.w + c.w + d4.w;
        int deg = end - beg;
        float inv = (deg > 0) ? 1.0f / (float)deg : 0.0f;
        float4 bv = *(const float4*)(bl + lane * 4);
        float4 rv = *(const float4*)(g_root + (size_t)n * NF + lane * 4);
        float4 o;
        o.x = fmaxf(a.x * inv + bv.x + rv.x, 0.0f);
        o.y = fmaxf(a.y * inv + bv.y + rv.y, 0.0f);
        o.z = fmaxf(a.z * inv + bv.z + rv.z, 0.0f);
        o.w = fmaxf(a.w * inv + bv.w + rv.w, 0.0f);
        *(float4*)(xout + (size_t)n * NF + lane * 4) = o;
    }
}

// ---------------- head: per-node dot with W_out, pooled per graph ----------------
__global__ void final_dot_kernel(const float* __restrict__ Wout,
                                 const int* __restrict__ batch) {
    int warp = (blockIdx.x * blockDim.x + threadIdx.x) >> 5;
    int lane = threadIdx.x & 31;
    if (warp >= NN) return;
    float4 a = *(const float4*)(g_bufA + (size_t)warp * NF + lane * 4);
    float4 w = *(const float4*)(Wout + lane * 4);
    float s = a.x * w.x + a.y * w.y + a.z * w.z + a.w * w.w;
    #pragma unroll
    for (int o = 16; o; o >>= 1) s += __shfl_xor_sync(0xFFFFFFFFu, s, o);
    if (lane == 0) {
        int b = batch[warp];
        if (b >= 0 && b < NG) atomicAdd(&g_gsum[b], s);
    }
}

__global__ void final_out_kernel(float* __restrict__ out, const float* __restrict__ b_out) {
    int g = blockIdx.x * blockDim.x + threadIdx.x;
    if (g < NG) {
        float c = fmaxf((float)g_gcnt[g], 1.0f);
        out[g] = g_gsum[g] / c + b_out[0];
    }
}

// ---------------- host launcher ----------------
extern "C" void kernel_launch(void* const* d_in, const int* in_sizes, int n_in,
                              void* d_out, int out_size) {
    const float* x     = (const float*)d_in[0];
    const int*   ei    = (const int*)d_in[1];
    const int*   batch = (const int*)d_in[2];
    const float* Wl[3] = { (const float*)d_in[3], (const float*)d_in[6], (const float*)d_in[9]  };
    const float* bl[3] = { (const float*)d_in[4], (const float*)d_in[7], (const float*)d_in[10] };
    const float* Wr[3] = { (const float*)d_in[5], (const float*)d_in[8], (const float*)d_in[11] };
    const float* W_out = (const float*)d_in[12];
    const float* b_out = (const float*)d_in[13];
    float* out = (float*)d_out;

    static int smem_set = 0;
    if (!smem_set) {
        cudaFuncSetAttribute(gemm2_kernel, cudaFuncAttributeMaxDynamicSharedMemorySize,
                             GEMM_SMEM_BYTES);
        smem_set = 1;
    }

    // CSR build
    zero_kernel<<<(NN + 255) / 256, 256>>>();
    hist_kernel<<<(NE + 255) / 256, 256>>>(ei, batch);
    scan_kernel<<<1, 1024>>>();
    scatter_kernel<<<(NE + 255) / 256, 256>>>(ei);

    // 3 SAGE layers
    dim3 ggrid((NN + MT - 1) / MT, 2);
    for (int l = 0; l < 3; l++) {
        gemm2_kernel<<<ggrid, 256, GEMM_SMEM_BYTES>>>(l, x, Wl[l], Wr[l]);
        agg_kernel<<<NN, 128>>>(l, bl[l]);
    }

    // head: dot + pooled mean + bias
    final_dot_kernel<<<(NN * 32 + 255) / 256, 256>>>(W_out, batch);
    final_out_kernel<<<(NG + 255) / 256, 256>>>(out, b_out);
}

// round 6
// speedup vs baseline: 1.9927x; 1.5407x over previous
#include <cuda_runtime.h>
#include <cuda_bf16.h>
#include <cstdint>
#include <cstddef>

#define NN 50000
#define NE 600000
#define NF 128
#define NG 500

// ---------------- device scratch (static, no allocation) ----------------
__device__ float g_bufA[NN * NF];
__device__ float g_bufB[NN * NF];
__device__ float g_lin[NN * NF];   // x @ Wl
__device__ float g_root[NN * NF];  // x @ Wr
__device__ int   g_deg[NN];
__device__ int   g_off[NN + 1];
__device__ int   g_cur[NN];
__device__ int   g_esrc[NE];
__device__ float g_gsum[NG];
__device__ int   g_gcnt[NG];
// pre-split, pre-transposed weights: [mat][n][k] bf16, mat = layer*2 + (0:Wl,1:Wr)
__device__ __nv_bfloat16 g_Wt_hi[6 * 128 * 128];
__device__ __nv_bfloat16 g_Wt_lo[6 * 128 * 128];

__device__ __forceinline__ void bsplit(float v, uint16_t& h, uint16_t& l) {
    __nv_bfloat16 hb = __float2bfloat16_rn(v);
    float hf = __bfloat162float(hb);
    __nv_bfloat16 lb = __float2bfloat16_rn(v - hf);
    h = __bfloat16_as_ushort(hb);
    l = __bfloat16_as_ushort(lb);
}
__device__ __forceinline__ uint32_t pack2(uint16_t a, uint16_t b) {
    return (uint32_t)a | ((uint32_t)b << 16);
}

// ---------------- weight prep: split fp32 -> bf16 hi/lo, transpose to [n][k] ----
__global__ void prep_w_kernel(const float* W0, const float* W1, const float* W2,
                              const float* W3, const float* W4, const float* W5) {
    const float* Ws[6] = { W0, W1, W2, W3, W4, W5 };
    int mat = blockIdx.y;
    const float* W = Ws[mat];
    int i = blockIdx.x * blockDim.x + threadIdx.x;   // 0..16383
    int k = i >> 7, n = i & 127;
    float v = W[i];
    uint16_t h, l;
    bsplit(v, h, l);
    int o = mat * 16384 + n * 128 + k;
    g_Wt_hi[o] = __ushort_as_bfloat16(h);
    g_Wt_lo[o] = __ushort_as_bfloat16(l);
}

// ---------------- CSR build ----------------
__global__ void zero_kernel() {
    int i = blockIdx.x * blockDim.x + threadIdx.x;
    if (i < NN) g_deg[i] = 0;
    if (i < NG) { g_gcnt[i] = 0; g_gsum[i] = 0.0f; }
}

__global__ void hist_kernel(const int* __restrict__ ei, const int* __restrict__ batch) {
    int base = (blockIdx.x * blockDim.x + threadIdx.x) * 4;
    #pragma unroll
    for (int j = 0; j < 4; j++) {
        int i = base + j;
        if (i < NE) {
            int d = ei[NE + i];
            if (d >= 0 && d < NN) atomicAdd(&g_deg[d], 1);
        }
        if (i < NN) {
            int b = batch[i];
            if (b >= 0 && b < NG) atomicAdd(&g_gcnt[b], 1);
        }
    }
}

__global__ void scan_kernel() {
    __shared__ int warpsum[32];
    __shared__ int s_carry;
    int tid = threadIdx.x, lane = tid & 31, wid = tid >> 5;
    if (tid == 0) s_carry = 0;
    __syncthreads();
    for (int base = 0; base < NN; base += 1024) {
        int i = base + tid;
        int v = (i < NN) ? g_deg[i] : 0;
        int x = v;
        #pragma unroll
        for (int o = 1; o < 32; o <<= 1) {
            int t = __shfl_up_sync(0xFFFFFFFFu, x, o);
            if (lane >= o) x += t;
        }
        if (lane == 31) warpsum[wid] = x;
        __syncthreads();
        if (wid == 0) {
            int y = warpsum[lane];
            #pragma unroll
            for (int o = 1; o < 32; o <<= 1) {
                int t = __shfl_up_sync(0xFFFFFFFFu, y, o);
                if (lane >= o) y += t;
            }
            warpsum[lane] = y;
        }
        __syncthreads();
        int wprefix = (wid > 0) ? warpsum[wid - 1] : 0;
        int excl = x - v + wprefix + s_carry;
        if (i < NN) { g_off[i] = excl; g_cur[i] = excl; }
        __syncthreads();
        if (tid == 0) s_carry += warpsum[31];
        __syncthreads();
    }
    if (threadIdx.x == 0) g_off[NN] = NE;
}

__global__ void scatter_kernel(const int* __restrict__ ei) {
    int base = (blockIdx.x * blockDim.x + threadIdx.x) * 4;
    #pragma unroll
    for (int j = 0; j < 4; j++) {
        int i = base + j;
        if (i < NE) {
            int s = ei[i];
            int d = ei[NE + i];
            if (d >= 0 && d < NN) {
                int p = atomicAdd(&g_cur[d], 1);
                g_esrc[p] = s;
            }
        }
    }
}

// ---------------- bf16x2 tensor-core GEMM: out = src @ W (fp32-accurate) --------
// M-tile 64, N=128. blockIdx.y: 0 -> g_lin (Wl), 1 -> g_root (Wr)
#define MT 64
#define SA 136                         // bf16 stride, A rows  (r*68+t banks distinct)
#define SB 136                         // bf16 stride, B n-rows
#define A_ELEMS (64 * SA)              // 8704
#define B_ELEMS (128 * SB)             // 17408
#define GEMM_SMEM ((2 * A_ELEMS + 2 * B_ELEMS) * 2)   // 104448 bytes

__device__ __forceinline__ void mma_bf16(float* c, const uint32_t* a, const uint32_t* b) {
    asm volatile(
        "mma.sync.aligned.m16n8k16.row.col.f32.bf16.bf16.f32 "
        "{%0,%1,%2,%3}, {%4,%5,%6,%7}, {%8,%9}, {%0,%1,%2,%3};"
        : "+f"(c[0]), "+f"(c[1]), "+f"(c[2]), "+f"(c[3])
        : "r"(a[0]), "r"(a[1]), "r"(a[2]), "r"(a[3]), "r"(b[0]), "r"(b[1]));
}

__global__ __launch_bounds__(256, 2) void gemm2_kernel(int layer,
                                                       const float* __restrict__ X) {
    extern __shared__ uint16_t sm16[];
    uint16_t* Ah = sm16;
    uint16_t* Al = Ah + A_ELEMS;
    uint16_t* Bh = Al + A_ELEMS;
    uint16_t* Bl = Bh + B_ELEMS;

    const float* src = (layer == 0) ? X : ((layer == 1) ? g_bufA : g_bufB);
    float* outp = blockIdx.y ? g_root : g_lin;
    int mat = layer * 2 + blockIdx.y;
    const __nv_bfloat16* wt_h = g_Wt_hi + mat * 16384;
    const __nv_bfloat16* wt_l = g_Wt_lo + mat * 16384;

    int tid = threadIdx.x, lane = tid & 31, wid = tid >> 5;
    int row0 = blockIdx.x * MT;

    // ---- fill A (64x128 fp32 -> bf16 hi/lo) ----
    #pragma unroll
    for (int i = 0; i < 8; i++) {
        int slot = tid + i * 256;          // 0..2047 float4 slots
        int r = slot >> 5;
        int c = (slot & 31) << 2;
        float4 v = make_float4(0.f, 0.f, 0.f, 0.f);
        if (row0 + r < NN) v = *(const float4*)(src + (size_t)(row0 + r) * NF + c);
        uint16_t hx, lx, hy, ly, hz, lz, hw, lw;
        bsplit(v.x, hx, lx); bsplit(v.y, hy, ly);
        bsplit(v.z, hz, lz); bsplit(v.w, hw, lw);
        uint2 hp, lp;
        hp.x = pack2(hx, hy); hp.y = pack2(hz, hw);
        lp.x = pack2(lx, ly); lp.y = pack2(lz, lw);
        *(uint2*)&Ah[r * SA + c] = hp;
        *(uint2*)&Al[r * SA + c] = lp;
    }
    // ---- fill B (pre-split [n][k] bf16, straight copy) ----
    #pragma unroll
    for (int i = 0; i < 8; i++) {
        int slot = tid + i * 256;          // 0..2047 uint4 slots (8 bf16 each)
        int n = slot >> 4;
        int c8 = (slot & 15) << 3;
        *(uint4*)&Bh[n * SB + c8] = *(const uint4*)&wt_h[n * 128 + c8];
        *(uint4*)&Bl[n * SB + c8] = *(const uint4*)&wt_l[n * 128 + c8];
    }
    __syncthreads();

    // warp tiling: 2 (M) x 4 (N), warp tile 32x32
    int warp_m = wid >> 2;
    int warp_n = wid & 3;
    int m_base = warp_m * 32;
    int n_base = warp_n * 32;
    int g = lane >> 2;     // group 0..7
    int t = lane & 3;      // 0..3

    float c[2][4][4];
    #pragma unroll
    for (int mi = 0; mi < 2; mi++)
        #pragma unroll
        for (int ni = 0; ni < 4; ni++)
            #pragma unroll
            for (int j = 0; j < 4; j++) c[mi][ni][j] = 0.0f;

    #pragma unroll
    for (int ks = 0; ks < 8; ks++) {
        int k0 = ks * 16;
        uint32_t ah[2][4], al[2][4];
        #pragma unroll
        for (int mi = 0; mi < 2; mi++) {
            int r = m_base + mi * 16 + g;
            ah[mi][0] = *(const uint32_t*)&Ah[r * SA + k0 + 2 * t];
            ah[mi][1] = *(const uint32_t*)&Ah[(r + 8) * SA + k0 + 2 * t];
            ah[mi][2] = *(const uint32_t*)&Ah[r * SA + k0 + 2 * t + 8];
            ah[mi][3] = *(const uint32_t*)&Ah[(r + 8) * SA + k0 + 2 * t + 8];
            al[mi][0] = *(const uint32_t*)&Al[r * SA + k0 + 2 * t];
            al[mi][1] = *(const uint32_t*)&Al[(r + 8) * SA + k0 + 2 * t];
            al[mi][2] = *(const uint32_t*)&Al[r * SA + k0 + 2 * t + 8];
            al[mi][3] = *(const uint32_t*)&Al[(r + 8) * SA + k0 + 2 * t + 8];
        }
        uint32_t bh[4][2], blo[4][2];
        #pragma unroll
        for (int ni = 0; ni < 4; ni++) {
            int n = n_base + ni * 8 + g;
            bh[ni][0]  = *(const uint32_t*)&Bh[n * SB + k0 + 2 * t];
            bh[ni][1]  = *(const uint32_t*)&Bh[n * SB + k0 + 2 * t + 8];
            blo[ni][0] = *(const uint32_t*)&Bl[n * SB + k0 + 2 * t];
            blo[ni][1] = *(const uint32_t*)&Bl[n * SB + k0 + 2 * t + 8];
        }
        #pragma unroll
        for (int mi = 0; mi < 2; mi++)
            #pragma unroll
            for (int ni = 0; ni < 4; ni++) {
                mma_bf16(c[mi][ni], ah[mi], bh[ni]);
                mma_bf16(c[mi][ni], ah[mi], blo[ni]);
                mma_bf16(c[mi][ni], al[mi], bh[ni]);
            }
    }

    // epilogue
    #pragma unroll
    for (int mi = 0; mi < 2; mi++) {
        int r0 = row0 + m_base + mi * 16 + g;
        int r1 = r0 + 8;
        #pragma unroll
        for (int ni = 0; ni < 4; ni++) {
            int col = n_base + ni * 8 + 2 * t;
            if (r0 < NN)
                *(float2*)(outp + (size_t)r0 * NF + col) = make_float2(c[mi][ni][0], c[mi][ni][1]);
            if (r1 < NN)
                *(float2*)(outp + (size_t)r1 * NF + col) = make_float2(c[mi][ni][2], c[mi][ni][3]);
        }
    }
}

// ---------------- aggregation: warp-per-node, dst = relu(mean_in(lin)+bl+root) ---
__global__ __launch_bounds__(256) void agg_kernel(int layer, const float* __restrict__ bl) {
    float* xout = (layer == 1) ? g_bufB : g_bufA;
    int wid = threadIdx.x >> 5, lane = threadIdx.x & 31;
    int n = blockIdx.x * 8 + wid;
    if (n >= NN) return;
    int beg = g_off[n], end = g_off[n + 1];
    float4 acc = make_float4(0.f, 0.f, 0.f, 0.f);
    int e = beg;
    for (; e + 2 <= end; e += 2) {
        int s0 = g_esrc[e], s1 = g_esrc[e + 1];
        float4 v0 = *(const float4*)(g_lin + (size_t)s0 * NF + lane * 4);
        float4 v1 = *(const float4*)(g_lin + (size_t)s1 * NF + lane * 4);
        acc.x += v0.x + v1.x; acc.y += v0.y + v1.y;
        acc.z += v0.z + v1.z; acc.w += v0.w + v1.w;
    }
    if (e < end) {
        float4 v = *(const float4*)(g_lin + (size_t)g_esrc[e] * NF + lane * 4);
        acc.x += v.x; acc.y += v.y; acc.z += v.z; acc.w += v.w;
    }
    int deg = end - beg;
    float inv = (deg > 0) ? 1.0f / (float)deg : 0.0f;
    float4 bv = *(const float4*)(bl + lane * 4);
    float4 rv = *(const float4*)(g_root + (size_t)n * NF + lane * 4);
    float4 o;
    o.x = fmaxf(acc.x * inv + bv.x + rv.x, 0.0f);
    o.y = fmaxf(acc.y * inv + bv.y + rv.y, 0.0f);
    o.z = fmaxf(acc.z * inv + bv.z + rv.z, 0.0f);
    o.w = fmaxf(acc.w * inv + bv.w + rv.w, 0.0f);
    *(float4*)(xout + (size_t)n * NF + lane * 4) = o;
}

// ---------------- head: per-node dot with W_out, pooled per graph ----------------
__global__ void final_dot_kernel(const float* __restrict__ Wout,
                                 const int* __restrict__ batch) {
    int warp = (blockIdx.x * blockDim.x + threadIdx.x) >> 5;
    int lane = threadIdx.x & 31;
    if (warp >= NN) return;
    float4 a = *(const float4*)(g_bufA + (size_t)warp * NF + lane * 4);
    float4 w = *(const float4*)(Wout + lane * 4);
    float s = a.x * w.x + a.y * w.y + a.z * w.z + a.w * w.w;
    #pragma unroll
    for (int o = 16; o; o >>= 1) s += __shfl_xor_sync(0xFFFFFFFFu, s, o);
    if (lane == 0) {
        int b = batch[warp];
        if (b >= 0 && b < NG) atomicAdd(&g_gsum[b], s);
    }
}

__global__ void final_out_kernel(float* __restrict__ out, const float* __restrict__ b_out) {
    int g = blockIdx.x * blockDim.x + threadIdx.x;
    if (g < NG) {
        float c = fmaxf((float)g_gcnt[g], 1.0f);
        out[g] = g_gsum[g] / c + b_out[0];
    }
}

// ---------------- host launcher ----------------
extern "C" void kernel_launch(void* const* d_in, const int* in_sizes, int n_in,
                              void* d_out, int out_size) {
    const float* x     = (const float*)d_in[0];
    const int*   ei    = (const int*)d_in[1];
    const int*   batch = (const int*)d_in[2];
    const float* Wl[3] = { (const float*)d_in[3], (const float*)d_in[6], (const float*)d_in[9]  };
    const float* bl[3] = { (const float*)d_in[4], (const float*)d_in[7], (const float*)d_in[10] };
    const float* Wr[3] = { (const float*)d_in[5], (const float*)d_in[8], (const float*)d_in[11] };
    const float* W_out = (const float*)d_in[12];
    const float* b_out = (const float*)d_in[13];
    float* out = (float*)d_out;

    static int smem_set = 0;
    if (!smem_set) {
        cudaFuncSetAttribute(gemm2_kernel, cudaFuncAttributeMaxDynamicSharedMemorySize,
                             GEMM_SMEM);
        smem_set = 1;
    }

    // weight prep (runs every launch; deterministic)
    dim3 wgrid(64, 6);
    prep_w_kernel<<<wgrid, 256>>>(Wl[0], Wr[0], Wl[1], Wr[1], Wl[2], Wr[2]);

    // CSR build
    zero_kernel<<<(NN + 255) / 256, 256>>>();
    hist_kernel<<<(NE + 1023) / 1024, 256>>>(ei, batch);
    scan_kernel<<<1, 1024>>>();
    scatter_kernel<<<(NE + 1023) / 1024, 256>>>(ei);

    // 3 SAGE layers
    dim3 ggrid((NN + MT - 1) / MT, 2);
    for (int l = 0; l < 3; l++) {
        gemm2_kernel<<<ggrid, 256, GEMM_SMEM>>>(l, x);
        agg_kernel<<<(NN + 7) / 8, 256>>>(l, bl[l]);
    }

    // head: dot + pooled mean + bias
    final_dot_kernel<<<(NN * 32 + 255) / 256, 256>>>(W_out, batch);
    final_out_kernel<<<(NG + 255) / 256, 256>>>(out, b_out);
}

// round 7
// speedup vs baseline: 2.3509x; 1.1798x over previous
#include <cuda_runtime.h>
#include <cuda_bf16.h>
#include <cstdint>
#include <cstddef>

#define NN 50000
#define NE 600000
#define NF 128
#define NG 500
#define NB_SCAN 49   // ceil(50000/1024)

// ---------------- device scratch (static, no allocation) ----------------
__device__ float g_bufA[NN * NF];
__device__ float g_bufB[NN * NF];
__device__ float g_lin[NN * NF];   // x @ Wl
__device__ float g_root[NN * NF];  // x @ Wr
__device__ int   g_deg[NN];
__device__ int   g_off[NN + 1];
__device__ int   g_cur[NN];
__device__ int   g_esrc[NE];
__device__ float g_gsum[NG];
__device__ int   g_gcnt[NG];
__device__ int   g_bsum[64];
__device__ int   g_bpre[64];
// pre-split, pre-transposed weights: [mat][n][k] bf16, mat = layer*2 + (0:Wl,1:Wr)
__device__ __nv_bfloat16 g_Wt_hi[6 * 128 * 128];
__device__ __nv_bfloat16 g_Wt_lo[6 * 128 * 128];

__device__ __forceinline__ void bsplit(float v, uint16_t& h, uint16_t& l) {
    __nv_bfloat16 hb = __float2bfloat16_rn(v);
    float hf = __bfloat162float(hb);
    __nv_bfloat16 lb = __float2bfloat16_rn(v - hf);
    h = __bfloat16_as_ushort(hb);
    l = __bfloat16_as_ushort(lb);
}
__device__ __forceinline__ uint32_t pack2(uint16_t a, uint16_t b) {
    return (uint32_t)a | ((uint32_t)b << 16);
}

// ---------------- weight prep: split fp32 -> bf16 hi/lo, transpose to [n][k] ----
__global__ void prep_w_kernel(const float* W0, const float* W1, const float* W2,
                              const float* W3, const float* W4, const float* W5) {
    const float* Ws[6] = { W0, W1, W2, W3, W4, W5 };
    int mat = blockIdx.y;
    const float* W = Ws[mat];
    int i = blockIdx.x * blockDim.x + threadIdx.x;   // 0..16383
    int k = i >> 7, n = i & 127;
    float v = W[i];
    uint16_t h, l;
    bsplit(v, h, l);
    int o = mat * 16384 + n * 128 + k;
    g_Wt_hi[o] = __ushort_as_bfloat16(h);
    g_Wt_lo[o] = __ushort_as_bfloat16(l);
}

// ---------------- CSR build ----------------
__global__ void zero_kernel() {
    int i = blockIdx.x * blockDim.x + threadIdx.x;
    if (i < NN) g_deg[i] = 0;
    if (i < NG) { g_gcnt[i] = 0; g_gsum[i] = 0.0f; }
}

__global__ void hist_kernel(const int* __restrict__ ei, const int* __restrict__ batch) {
    int base = (blockIdx.x * blockDim.x + threadIdx.x) * 4;
    #pragma unroll
    for (int j = 0; j < 4; j++) {
        int i = base + j;
        if (i < NE) {
            int d = ei[NE + i];
            if (d >= 0 && d < NN) atomicAdd(&g_deg[d], 1);
        }
        if (i < NN) {
            int b = batch[i];
            if (b >= 0 && b < NG) atomicAdd(&g_gcnt[b], 1);
        }
    }
}

// P1: per-block local scan of 1024 elements, emit block total
__global__ __launch_bounds__(1024) void scan1_kernel() {
    __shared__ int warpsum[32];
    int tid = threadIdx.x, lane = tid & 31, wid = tid >> 5;
    int i = blockIdx.x * 1024 + tid;
    int v = (i < NN) ? g_deg[i] : 0;
    int x = v;
    #pragma unroll
    for (int o = 1; o < 32; o <<= 1) {
        int t = __shfl_up_sync(0xFFFFFFFFu, x, o);
        if (lane >= o) x += t;
    }
    if (lane == 31) warpsum[wid] = x;
    __syncthreads();
    if (wid == 0) {
        int y = warpsum[lane];
        #pragma unroll
        for (int o = 1; o < 32; o <<= 1) {
            int t = __shfl_up_sync(0xFFFFFFFFu, y, o);
            if (lane >= o) y += t;
        }
        warpsum[lane] = y;
    }
    __syncthreads();
    int wprefix = (wid > 0) ? warpsum[wid - 1] : 0;
    if (i < NN) g_off[i] = x - v + wprefix;     // local exclusive
    if (tid == 1023) g_bsum[blockIdx.x] = wprefix + x;
}

// P2: single warp scans the block sums (<=64)
__global__ void scan2_kernel() {
    int lane = threadIdx.x;   // 32 threads
    int v0 = (lane < NB_SCAN) ? g_bsum[lane] : 0;
    int x0 = v0;
    #pragma unroll
    for (int o = 1; o < 32; o <<= 1) {
        int t = __shfl_up_sync(0xFFFFFFFFu, x0, o);
        if (lane >= o) x0 += t;
    }
    int tot0 = __shfl_sync(0xFFFFFFFFu, x0, 31);
    int i1 = lane + 32;
    int v1 = (i1 < NB_SCAN) ? g_bsum[i1] : 0;
    int x1 = v1;
    #pragma unroll
    for (int o = 1; o < 32; o <<= 1) {
        int t = __shfl_up_sync(0xFFFFFFFFu, x1, o);
        if (lane >= o) x1 += t;
    }
    g_bpre[lane] = x0 - v0;
    g_bpre[i1] = x1 - v1 + tot0;
    if (lane == 0) g_off[NN] = NE;
}

// P3: add block prefix, mirror to g_cur
__global__ __launch_bounds__(1024) void scan3_kernel() {
    int i = blockIdx.x * 1024 + threadIdx.x;
    if (i < NN) {
        int o = g_off[i] + g_bpre[blockIdx.x];
        g_off[i] = o;
        g_cur[i] = o;
    }
}

__global__ void scatter_kernel(const int* __restrict__ ei) {
    int base = (blockIdx.x * blockDim.x + threadIdx.x) * 4;
    #pragma unroll
    for (int j = 0; j < 4; j++) {
        int i = base + j;
        if (i < NE) {
            int s = ei[i];
            int d = ei[NE + i];
            if (d >= 0 && d < NN) {
                int p = atomicAdd(&g_cur[d], 1);
                g_esrc[p] = s;
            }
        }
    }
}

// ---------------- bf16x2 tensor-core GEMM: out = src @ W (fp32-accurate) --------
// M-tile 64, N=128. blockIdx.y: 0 -> g_lin (Wl), 1 -> g_root (Wr)
#define MT 64
#define SA 136
#define SB 136
#define A_ELEMS (64 * SA)
#define B_ELEMS (128 * SB)
#define GEMM_SMEM ((2 * A_ELEMS + 2 * B_ELEMS) * 2)   // 104448 bytes

__device__ __forceinline__ void mma_bf16(float* c, const uint32_t* a, const uint32_t* b) {
    asm volatile(
        "mma.sync.aligned.m16n8k16.row.col.f32.bf16.bf16.f32 "
        "{%0,%1,%2,%3}, {%4,%5,%6,%7}, {%8,%9}, {%0,%1,%2,%3};"
        : "+f"(c[0]), "+f"(c[1]), "+f"(c[2]), "+f"(c[3])
        : "r"(a[0]), "r"(a[1]), "r"(a[2]), "r"(a[3]), "r"(b[0]), "r"(b[1]));
}

__global__ __launch_bounds__(256, 2) void gemm2_kernel(int layer,
                                                       const float* __restrict__ X) {
    extern __shared__ uint16_t sm16[];
    uint16_t* Ah = sm16;
    uint16_t* Al = Ah + A_ELEMS;
    uint16_t* Bh = Al + A_ELEMS;
    uint16_t* Bl = Bh + B_ELEMS;

    const float* src = (layer == 0) ? X : ((layer == 1) ? g_bufA : g_bufB);
    float* outp = blockIdx.y ? g_root : g_lin;
    int mat = layer * 2 + blockIdx.y;
    const __nv_bfloat16* wt_h = g_Wt_hi + mat * 16384;
    const __nv_bfloat16* wt_l = g_Wt_lo + mat * 16384;

    int tid = threadIdx.x, lane = tid & 31, wid = tid >> 5;
    int row0 = blockIdx.x * MT;

    // ---- fill A (64x128 fp32 -> bf16 hi/lo) ----
    #pragma unroll
    for (int i = 0; i < 8; i++) {
        int slot = tid + i * 256;
        int r = slot >> 5;
        int c = (slot & 31) << 2;
        float4 v = make_float4(0.f, 0.f, 0.f, 0.f);
        if (row0 + r < NN) v = *(const float4*)(src + (size_t)(row0 + r) * NF + c);
        uint16_t hx, lx, hy, ly, hz, lz, hw, lw;
        bsplit(v.x, hx, lx); bsplit(v.y, hy, ly);
        bsplit(v.z, hz, lz); bsplit(v.w, hw, lw);
        uint2 hp, lp;
        hp.x = pack2(hx, hy); hp.y = pack2(hz, hw);
        lp.x = pack2(lx, ly); lp.y = pack2(lz, lw);
        *(uint2*)&Ah[r * SA + c] = hp;
        *(uint2*)&Al[r * SA + c] = lp;
    }
    // ---- fill B (pre-split [n][k] bf16, straight copy) ----
    #pragma unroll
    for (int i = 0; i < 8; i++) {
        int slot = tid + i * 256;
        int n = slot >> 4;
        int c8 = (slot & 15) << 3;
        *(uint4*)&Bh[n * SB + c8] = *(const uint4*)&wt_h[n * 128 + c8];
        *(uint4*)&Bl[n * SB + c8] = *(const uint4*)&wt_l[n * 128 + c8];
    }
    __syncthreads();

    int warp_m = wid >> 2;
    int warp_n = wid & 3;
    int m_base = warp_m * 32;
    int n_base = warp_n * 32;
    int g = lane >> 2;
    int t = lane & 3;

    float c[2][4][4];
    #pragma unroll
    for (int mi = 0; mi < 2; mi++)
        #pragma unroll
        for (int ni = 0; ni < 4; ni++)
            #pragma unroll
            for (int j = 0; j < 4; j++) c[mi][ni][j] = 0.0f;

    #pragma unroll
    for (int ks = 0; ks < 8; ks++) {
        int k0 = ks * 16;
        uint32_t ah[2][4], al[2][4];
        #pragma unroll
        for (int mi = 0; mi < 2; mi++) {
            int r = m_base + mi * 16 + g;
            ah[mi][0] = *(const uint32_t*)&Ah[r * SA + k0 + 2 * t];
            ah[mi][1] = *(const uint32_t*)&Ah[(r + 8) * SA + k0 + 2 * t];
            ah[mi][2] = *(const uint32_t*)&Ah[r * SA + k0 + 2 * t + 8];
            ah[mi][3] = *(const uint32_t*)&Ah[(r + 8) * SA + k0 + 2 * t + 8];
            al[mi][0] = *(const uint32_t*)&Al[r * SA + k0 + 2 * t];
            al[mi][1] = *(const uint32_t*)&Al[(r + 8) * SA + k0 + 2 * t];
            al[mi][2] = *(const uint32_t*)&Al[r * SA + k0 + 2 * t + 8];
            al[mi][3] = *(const uint32_t*)&Al[(r + 8) * SA + k0 + 2 * t + 8];
        }
        uint32_t bh[4][2], blo[4][2];
        #pragma unroll
        for (int ni = 0; ni < 4; ni++) {
            int n = n_base + ni * 8 + g;
            bh[ni][0]  = *(const uint32_t*)&Bh[n * SB + k0 + 2 * t];
            bh[ni][1]  = *(const uint32_t*)&Bh[n * SB + k0 + 2 * t + 8];
            blo[ni][0] = *(const uint32_t*)&Bl[n * SB + k0 + 2 * t];
            blo[ni][1] = *(const uint32_t*)&Bl[n * SB + k0 + 2 * t + 8];
        }
        #pragma unroll
        for (int mi = 0; mi < 2; mi++)
            #pragma unroll
            for (int ni = 0; ni < 4; ni++) {
                mma_bf16(c[mi][ni], ah[mi], bh[ni]);
                mma_bf16(c[mi][ni], ah[mi], blo[ni]);
                mma_bf16(c[mi][ni], al[mi], bh[ni]);
            }
    }

    #pragma unroll
    for (int mi = 0; mi < 2; mi++) {
        int r0 = row0 + m_base + mi * 16 + g;
        int r1 = r0 + 8;
        #pragma unroll
        for (int ni = 0; ni < 4; ni++) {
            int col = n_base + ni * 8 + 2 * t;
            if (r0 < NN)
                *(float2*)(outp + (size_t)r0 * NF + col) = make_float2(c[mi][ni][0], c[mi][ni][1]);
            if (r1 < NN)
                *(float2*)(outp + (size_t)r1 * NF + col) = make_float2(c[mi][ni][2], c[mi][ni][3]);
        }
    }
}

// ---------------- aggregation: warp-per-node, dst = relu(mean_in(lin)+bl+root) ---
// last=1: instead of storing xout, fuse head: dot with W_out, atomicAdd to g_gsum
__global__ __launch_bounds__(256) void agg_kernel(int layer, int last,
                                                  const float* __restrict__ bl,
                                                  const float* __restrict__ Wout,
                                                  const int* __restrict__ batch) {
    float* xout = (layer == 1) ? g_bufB : g_bufA;
    int wid = threadIdx.x >> 5, lane = threadIdx.x & 31;
    int n = blockIdx.x * 8 + wid;
    if (n >= NN) return;
    int beg = g_off[n], end = g_off[n + 1];
    float4 acc = make_float4(0.f, 0.f, 0.f, 0.f);
    int e = beg;
    for (; e + 2 <= end; e += 2) {
        int s0 = g_esrc[e], s1 = g_esrc[e + 1];
        float4 v0 = *(const float4*)(g_lin + (size_t)s0 * NF + lane * 4);
        float4 v1 = *(const float4*)(g_lin + (size_t)s1 * NF + lane * 4);
        acc.x += v0.x + v1.x; acc.y += v0.y + v1.y;
        acc.z += v0.z + v1.z; acc.w += v0.w + v1.w;
    }
    if (e < end) {
        float4 v = *(const float4*)(g_lin + (size_t)g_esrc[e] * NF + lane * 4);
        acc.x += v.x; acc.y += v.y; acc.z += v.z; acc.w += v.w;
    }
    int deg = end - beg;
    float inv = (deg > 0) ? 1.0f / (float)deg : 0.0f;
    float4 bv = *(const float4*)(bl + lane * 4);
    float4 rv = *(const float4*)(g_root + (size_t)n * NF + lane * 4);
    float4 o;
    o.x = fmaxf(acc.x * inv + bv.x + rv.x, 0.0f);
    o.y = fmaxf(acc.y * inv + bv.y + rv.y, 0.0f);
    o.z = fmaxf(acc.z * inv + bv.z + rv.z, 0.0f);
    o.w = fmaxf(acc.w * inv + bv.w + rv.w, 0.0f);
    if (!last) {
        *(float4*)(xout + (size_t)n * NF + lane * 4) = o;
    } else {
        float4 w = *(const float4*)(Wout + lane * 4);
        float s = o.x * w.x + o.y * w.y + o.z * w.z + o.w * w.w;
        #pragma unroll
        for (int off = 16; off; off >>= 1) s += __shfl_xor_sync(0xFFFFFFFFu, s, off);
        if (lane == 0) {
            int b = batch[n];
            if (b >= 0 && b < NG) atomicAdd(&g_gsum[b], s);
        }
    }
}

__global__ void final_out_kernel(float* __restrict__ out, const float* __restrict__ b_out) {
    int g = blockIdx.x * blockDim.x + threadIdx.x;
    if (g < NG) {
        float c = fmaxf((float)g_gcnt[g], 1.0f);
        out[g] = g_gsum[g] / c + b_out[0];
    }
}

// ---------------- host launcher ----------------
extern "C" void kernel_launch(void* const* d_in, const int* in_sizes, int n_in,
                              void* d_out, int out_size) {
    const float* x     = (const float*)d_in[0];
    const int*   ei    = (const int*)d_in[1];
    const int*   batch = (const int*)d_in[2];
    const float* Wl[3] = { (const float*)d_in[3], (const float*)d_in[6], (const float*)d_in[9]  };
    const float* bl[3] = { (const float*)d_in[4], (const float*)d_in[7], (const float*)d_in[10] };
    const float* Wr[3] = { (const float*)d_in[5], (const float*)d_in[8], (const float*)d_in[11] };
    const float* W_out = (const float*)d_in[12];
    const float* b_out = (const float*)d_in[13];
    float* out = (float*)d_out;

    static int smem_set = 0;
    if (!smem_set) {
        cudaFuncSetAttribute(gemm2_kernel, cudaFuncAttributeMaxDynamicSharedMemorySize,
                             GEMM_SMEM);
        smem_set = 1;
    }

    // weight prep
    dim3 wgrid(64, 6);
    prep_w_kernel<<<wgrid, 256>>>(Wl[0], Wr[0], Wl[1], Wr[1], Wl[2], Wr[2]);

    // CSR build
    zero_kernel<<<(NN + 255) / 256, 256>>>();
    hist_kernel<<<(NE + 1023) / 1024, 256>>>(ei, batch);
    scan1_kernel<<<NB_SCAN, 1024>>>();
    scan2_kernel<<<1, 32>>>();
    scan3_kernel<<<NB_SCAN, 1024>>>();
    scatter_kernel<<<(NE + 1023) / 1024, 256>>>(ei);

    // 3 SAGE layers (layer 2 fuses the output head)
    dim3 ggrid((NN + MT - 1) / MT, 2);
    for (int l = 0; l < 3; l++) {
        gemm2_kernel<<<ggrid, 256, GEMM_SMEM>>>(l, x);
        agg_kernel<<<(NN + 7) / 8, 256>>>(l, (l == 2) ? 1 : 0, bl[l], W_out, batch);
    }

    final_out_kernel<<<(NG + 255) / 256, 256>>>(out, b_out);
}

// round 8
// speedup vs baseline: 2.4550x; 1.0443x over previous
#include <cuda_runtime.h>
#include <cuda_bf16.h>
#include <cuda_fp16.h>
#include <cstdint>
#include <cstddef>

#define NN 50000
#define NE 600000
#define NF 128
#define NG 500
#define NB_SCAN 49   // ceil(50000/1024)

// ---------------- device scratch (static, no allocation) ----------------
__device__ float  g_bufA[NN * NF];
__device__ float  g_bufB[NN * NF];
__device__ __half g_lin16[NN * NF];   // x @ Wl  (fp16, gather-only)
__device__ float  g_root[NN * NF];    // x @ Wr
__device__ int    g_deg[NN];
__device__ int    g_off[NN + 1];
__device__ int    g_cur[NN];
__device__ int    g_esrc[NE];
__device__ float  g_gsum[NG];
__device__ int    g_gcnt[NG];
__device__ int    g_bsum[64];
__device__ int    g_bpre[64];
// pre-split, pre-transposed weights: [mat][n][k] bf16, mat = layer*2 + (0:Wl,1:Wr)
__device__ __nv_bfloat16 g_Wt_hi[6 * 128 * 128];
__device__ __nv_bfloat16 g_Wt_lo[6 * 128 * 128];

__device__ __forceinline__ void bsplit(float v, uint16_t& h, uint16_t& l) {
    __nv_bfloat16 hb = __float2bfloat16_rn(v);
    float hf = __bfloat162float(hb);
    __nv_bfloat16 lb = __float2bfloat16_rn(v - hf);
    h = __bfloat16_as_ushort(hb);
    l = __bfloat16_as_ushort(lb);
}
__device__ __forceinline__ uint32_t pack2(uint16_t a, uint16_t b) {
    return (uint32_t)a | ((uint32_t)b << 16);
}

// ---------------- weight prep ----------------
__global__ void prep_w_kernel(const float* W0, const float* W1, const float* W2,
                              const float* W3, const float* W4, const float* W5) {
    const float* Ws[6] = { W0, W1, W2, W3, W4, W5 };
    int mat = blockIdx.y;
    const float* W = Ws[mat];
    int i = blockIdx.x * blockDim.x + threadIdx.x;   // 0..16383
    int k = i >> 7, n = i & 127;
    float v = W[i];
    uint16_t h, l;
    bsplit(v, h, l);
    int o = mat * 16384 + n * 128 + k;
    g_Wt_hi[o] = __ushort_as_bfloat16(h);
    g_Wt_lo[o] = __ushort_as_bfloat16(l);
}

// ---------------- CSR build ----------------
__global__ void zero_kernel() {
    int i = blockIdx.x * blockDim.x + threadIdx.x;
    if (i < NN) g_deg[i] = 0;
    if (i < NG) { g_gcnt[i] = 0; g_gsum[i] = 0.0f; }
}

// NE and NN divisible by 4: int4 loads
__global__ void hist_kernel(const int* __restrict__ ei, const int* __restrict__ batch) {
    int idx = blockIdx.x * blockDim.x + threadIdx.x;
    if (idx < NE / 4) {
        int4 d4 = ((const int4*)(ei + NE))[idx];
        if (d4.x >= 0 && d4.x < NN) atomicAdd(&g_deg[d4.x], 1);
        if (d4.y >= 0 && d4.y < NN) atomicAdd(&g_deg[d4.y], 1);
        if (d4.z >= 0 && d4.z < NN) atomicAdd(&g_deg[d4.z], 1);
        if (d4.w >= 0 && d4.w < NN) atomicAdd(&g_deg[d4.w], 1);
    }
    if (idx < NN / 4) {
        int4 b4 = ((const int4*)batch)[idx];
        if (b4.x >= 0 && b4.x < NG) atomicAdd(&g_gcnt[b4.x], 1);
        if (b4.y >= 0 && b4.y < NG) atomicAdd(&g_gcnt[b4.y], 1);
        if (b4.z >= 0 && b4.z < NG) atomicAdd(&g_gcnt[b4.z], 1);
        if (b4.w >= 0 && b4.w < NG) atomicAdd(&g_gcnt[b4.w], 1);
    }
}

// P1: per-block local scan of 1024, emit block total
__global__ __launch_bounds__(1024) void scan1_kernel() {
    __shared__ int warpsum[32];
    int tid = threadIdx.x, lane = tid & 31, wid = tid >> 5;
    int i = blockIdx.x * 1024 + tid;
    int v = (i < NN) ? g_deg[i] : 0;
    int x = v;
    #pragma unroll
    for (int o = 1; o < 32; o <<= 1) {
        int t = __shfl_up_sync(0xFFFFFFFFu, x, o);
        if (lane >= o) x += t;
    }
    if (lane == 31) warpsum[wid] = x;
    __syncthreads();
    if (wid == 0) {
        int y = warpsum[lane];
        #pragma unroll
        for (int o = 1; o < 32; o <<= 1) {
            int t = __shfl_up_sync(0xFFFFFFFFu, y, o);
            if (lane >= o) y += t;
        }
        warpsum[lane] = y;
    }
    __syncthreads();
    int wprefix = (wid > 0) ? warpsum[wid - 1] : 0;
    if (i < NN) g_off[i] = x - v + wprefix;
    if (tid == 1023) g_bsum[blockIdx.x] = wprefix + x;
}

// P2: one warp scans block sums
__global__ void scan2_kernel() {
    int lane = threadIdx.x;
    int v0 = (lane < NB_SCAN) ? g_bsum[lane] : 0;
    int x0 = v0;
    #pragma unroll
    for (int o = 1; o < 32; o <<= 1) {
        int t = __shfl_up_sync(0xFFFFFFFFu, x0, o);
        if (lane >= o) x0 += t;
    }
    int tot0 = __shfl_sync(0xFFFFFFFFu, x0, 31);
    int i1 = lane + 32;
    int v1 = (i1 < NB_SCAN) ? g_bsum[i1] : 0;
    int x1 = v1;
    #pragma unroll
    for (int o = 1; o < 32; o <<= 1) {
        int t = __shfl_up_sync(0xFFFFFFFFu, x1, o);
        if (lane >= o) x1 += t;
    }
    g_bpre[lane] = x0 - v0;
    g_bpre[i1] = x1 - v1 + tot0;
    if (lane == 0) g_off[NN] = NE;
}

// P3: add block prefix, mirror to g_cur
__global__ __launch_bounds__(1024) void scan3_kernel() {
    int i = blockIdx.x * 1024 + threadIdx.x;
    if (i < NN) {
        int o = g_off[i] + g_bpre[blockIdx.x];
        g_off[i] = o;
        g_cur[i] = o;
    }
}

__global__ void scatter_kernel(const int* __restrict__ ei) {
    int idx = blockIdx.x * blockDim.x + threadIdx.x;
    if (idx < NE / 4) {
        int4 s4 = ((const int4*)ei)[idx];
        int4 d4 = ((const int4*)(ei + NE))[idx];
        if (d4.x >= 0 && d4.x < NN) g_esrc[atomicAdd(&g_cur[d4.x], 1)] = s4.x;
        if (d4.y >= 0 && d4.y < NN) g_esrc[atomicAdd(&g_cur[d4.y], 1)] = s4.y;
        if (d4.z >= 0 && d4.z < NN) g_esrc[atomicAdd(&g_cur[d4.z], 1)] = s4.z;
        if (d4.w >= 0 && d4.w < NN) g_esrc[atomicAdd(&g_cur[d4.w], 1)] = s4.w;
    }
}

// ---------------- bf16x2 tensor-core GEMM --------------------------------------
// M-tile 64, N=128. blockIdx.y: 0 -> g_lin16 (Wl, fp16 out), 1 -> g_root (Wr, fp32)
#define MT 64
#define SA 136
#define SB 136
#define A_ELEMS (64 * SA)
#define B_ELEMS (128 * SB)
#define GEMM_SMEM ((2 * A_ELEMS + 2 * B_ELEMS) * 2)   // 104448 bytes

__device__ __forceinline__ void mma_bf16(float* c, const uint32_t* a, const uint32_t* b) {
    asm volatile(
        "mma.sync.aligned.m16n8k16.row.col.f32.bf16.bf16.f32 "
        "{%0,%1,%2,%3}, {%4,%5,%6,%7}, {%8,%9}, {%0,%1,%2,%3};"
        : "+f"(c[0]), "+f"(c[1]), "+f"(c[2]), "+f"(c[3])
        : "r"(a[0]), "r"(a[1]), "r"(a[2]), "r"(a[3]), "r"(b[0]), "r"(b[1]));
}

__global__ __launch_bounds__(256, 2) void gemm2_kernel(int layer,
                                                       const float* __restrict__ X) {
    extern __shared__ uint16_t sm16[];
    uint16_t* Ah = sm16;
    uint16_t* Al = Ah + A_ELEMS;
    uint16_t* Bh = Al + A_ELEMS;
    uint16_t* Bl = Bh + B_ELEMS;

    const float* src = (layer == 0) ? X : ((layer == 1) ? g_bufA : g_bufB);
    int mat = layer * 2 + blockIdx.y;
    const __nv_bfloat16* wt_h = g_Wt_hi + mat * 16384;
    const __nv_bfloat16* wt_l = g_Wt_lo + mat * 16384;

    int tid = threadIdx.x, lane = tid & 31, wid = tid >> 5;
    int row0 = blockIdx.x * MT;

    #pragma unroll
    for (int i = 0; i < 8; i++) {
        int slot = tid + i * 256;
        int r = slot >> 5;
        int c = (slot & 31) << 2;
        float4 v = make_float4(0.f, 0.f, 0.f, 0.f);
        if (row0 + r < NN) v = *(const float4*)(src + (size_t)(row0 + r) * NF + c);
        uint16_t hx, lx, hy, ly, hz, lz, hw, lw;
        bsplit(v.x, hx, lx); bsplit(v.y, hy, ly);
        bsplit(v.z, hz, lz); bsplit(v.w, hw, lw);
        uint2 hp, lp;
        hp.x = pack2(hx, hy); hp.y = pack2(hz, hw);
        lp.x = pack2(lx, ly); lp.y = pack2(lz, lw);
        *(uint2*)&Ah[r * SA + c] = hp;
        *(uint2*)&Al[r * SA + c] = lp;
    }
    #pragma unroll
    for (int i = 0; i < 8; i++) {
        int slot = tid + i * 256;
        int n = slot >> 4;
        int c8 = (slot & 15) << 3;
        *(uint4*)&Bh[n * SB + c8] = *(const uint4*)&wt_h[n * 128 + c8];
        *(uint4*)&Bl[n * SB + c8] = *(const uint4*)&wt_l[n * 128 + c8];
    }
    __syncthreads();

    int warp_m = wid >> 2;
    int warp_n = wid & 3;
    int m_base = warp_m * 32;
    int n_base = warp_n * 32;
    int g = lane >> 2;
    int t = lane & 3;

    float c[2][4][4];
    #pragma unroll
    for (int mi = 0; mi < 2; mi++)
        #pragma unroll
        for (int ni = 0; ni < 4; ni++)
            #pragma unroll
            for (int j = 0; j < 4; j++) c[mi][ni][j] = 0.0f;

    #pragma unroll
    for (int ks = 0; ks < 8; ks++) {
        int k0 = ks * 16;
        uint32_t ah[2][4], al[2][4];
        #pragma unroll
        for (int mi = 0; mi < 2; mi++) {
            int r = m_base + mi * 16 + g;
            ah[mi][0] = *(const uint32_t*)&Ah[r * SA + k0 + 2 * t];
            ah[mi][1] = *(const uint32_t*)&Ah[(r + 8) * SA + k0 + 2 * t];
            ah[mi][2] = *(const uint32_t*)&Ah[r * SA + k0 + 2 * t + 8];
            ah[mi][3] = *(const uint32_t*)&Ah[(r + 8) * SA + k0 + 2 * t + 8];
            al[mi][0] = *(const uint32_t*)&Al[r * SA + k0 + 2 * t];
            al[mi][1] = *(const uint32_t*)&Al[(r + 8) * SA + k0 + 2 * t];
            al[mi][2] = *(const uint32_t*)&Al[r * SA + k0 + 2 * t + 8];
            al[mi][3] = *(const uint32_t*)&Al[(r + 8) * SA + k0 + 2 * t + 8];
        }
        uint32_t bh[4][2], blo[4][2];
        #pragma unroll
        for (int ni = 0; ni < 4; ni++) {
            int n = n_base + ni * 8 + g;
            bh[ni][0]  = *(const uint32_t*)&Bh[n * SB + k0 + 2 * t];
            bh[ni][1]  = *(const uint32_t*)&Bh[n * SB + k0 + 2 * t + 8];
            blo[ni][0] = *(const uint32_t*)&Bl[n * SB + k0 + 2 * t];
            blo[ni][1] = *(const uint32_t*)&Bl[n * SB + k0 + 2 * t + 8];
        }
        #pragma unroll
        for (int mi = 0; mi < 2; mi++)
            #pragma unroll
            for (int ni = 0; ni < 4; ni++) {
                mma_bf16(c[mi][ni], ah[mi], bh[ni]);
                mma_bf16(c[mi][ni], ah[mi], blo[ni]);
                mma_bf16(c[mi][ni], al[mi], bh[ni]);
            }
    }

    if (blockIdx.y == 0) {
        // lin output -> fp16 (gather-only consumer)
        #pragma unroll
        for (int mi = 0; mi < 2; mi++) {
            int r0 = row0 + m_base + mi * 16 + g;
            int r1 = r0 + 8;
            #pragma unroll
            for (int ni = 0; ni < 4; ni++) {
                int col = n_base + ni * 8 + 2 * t;
                if (r0 < NN)
                    *(__half2*)(g_lin16 + (size_t)r0 * NF + col) =
                        __floats2half2_rn(c[mi][ni][0], c[mi][ni][1]);
                if (r1 < NN)
                    *(__half2*)(g_lin16 + (size_t)r1 * NF + col) =
                        __floats2half2_rn(c[mi][ni][2], c[mi][ni][3]);
            }
        }
    } else {
        #pragma unroll
        for (int mi = 0; mi < 2; mi++) {
            int r0 = row0 + m_base + mi * 16 + g;
            int r1 = r0 + 8;
            #pragma unroll
            for (int ni = 0; ni < 4; ni++) {
                int col = n_base + ni * 8 + 2 * t;
                if (r0 < NN)
                    *(float2*)(g_root + (size_t)r0 * NF + col) = make_float2(c[mi][ni][0], c[mi][ni][1]);
                if (r1 < NN)
                    *(float2*)(g_root + (size_t)r1 * NF + col) = make_float2(c[mi][ni][2], c[mi][ni][3]);
            }
        }
    }
}

// ---------------- aggregation: warp-per-node, fp16 gather ------------------------
__global__ __launch_bounds__(256) void agg_kernel(int layer, int last,
                                                  const float* __restrict__ bl,
                                                  const float* __restrict__ Wout,
                                                  const int* __restrict__ batch) {
    float* xout = (layer == 1) ? g_bufB : g_bufA;
    int wid = threadIdx.x >> 5, lane = threadIdx.x & 31;
    int n = blockIdx.x * 8 + wid;
    if (n >= NN) return;
    int beg = g_off[n], end = g_off[n + 1];
    float4 acc = make_float4(0.f, 0.f, 0.f, 0.f);
    int e = beg;
    for (; e + 2 <= end; e += 2) {
        int s0 = g_esrc[e], s1 = g_esrc[e + 1];
        uint2 p0 = ((const uint2*)(g_lin16 + (size_t)s0 * NF))[lane];
        uint2 p1 = ((const uint2*)(g_lin16 + (size_t)s1 * NF))[lane];
        float2 a0 = __half22float2(*(__half2*)&p0.x);
        float2 b0 = __half22float2(*(__half2*)&p0.y);
        float2 a1 = __half22float2(*(__half2*)&p1.x);
        float2 b1 = __half22float2(*(__half2*)&p1.y);
        acc.x += a0.x + a1.x; acc.y += a0.y + a1.y;
        acc.z += b0.x + b1.x; acc.w += b0.y + b1.y;
    }
    if (e < end) {
        uint2 p = ((const uint2*)(g_lin16 + (size_t)g_esrc[e] * NF))[lane];
        float2 a = __half22float2(*(__half2*)&p.x);
        float2 b = __half22float2(*(__half2*)&p.y);
        acc.x += a.x; acc.y += a.y; acc.z += b.x; acc.w += b.y;
    }
    int deg = end - beg;
    float inv = (deg > 0) ? 1.0f / (float)deg : 0.0f;
    float4 bv = *(const float4*)(bl + lane * 4);
    float4 rv = *(const float4*)(g_root + (size_t)n * NF + lane * 4);
    float4 o;
    o.x = fmaxf(acc.x * inv + bv.x + rv.x, 0.0f);
    o.y = fmaxf(acc.y * inv + bv.y + rv.y, 0.0f);
    o.z = fmaxf(acc.z * inv + bv.z + rv.z, 0.0f);
    o.w = fmaxf(acc.w * inv + bv.w + rv.w, 0.0f);
    if (!last) {
        *(float4*)(xout + (size_t)n * NF + lane * 4) = o;
    } else {
        float4 w = *(const float4*)(Wout + lane * 4);
        float s = o.x * w.x + o.y * w.y + o.z * w.z + o.w * w.w;
        #pragma unroll
        for (int off = 16; off; off >>= 1) s += __shfl_xor_sync(0xFFFFFFFFu, s, off);
        if (lane == 0) {
            int b = batch[n];
            if (b >= 0 && b < NG) atomicAdd(&g_gsum[b], s);
        }
    }
}

__global__ void final_out_kernel(float* __restrict__ out, const float* __restrict__ b_out) {
    int g = blockIdx.x * blockDim.x + threadIdx.x;
    if (g < NG) {
        float c = fmaxf((float)g_gcnt[g], 1.0f);
        out[g] = g_gsum[g] / c + b_out[0];
    }
}

// ---------------- host launcher ----------------
extern "C" void kernel_launch(void* const* d_in, const int* in_sizes, int n_in,
                              void* d_out, int out_size) {
    const float* x     = (const float*)d_in[0];
    const int*   ei    = (const int*)d_in[1];
    const int*   batch = (const int*)d_in[2];
    const float* Wl[3] = { (const float*)d_in[3], (const float*)d_in[6], (const float*)d_in[9]  };
    const float* bl[3] = { (const float*)d_in[4], (const float*)d_in[7], (const float*)d_in[10] };
    const float* Wr[3] = { (const float*)d_in[5], (const float*)d_in[8], (const float*)d_in[11] };
    const float* W_out = (const float*)d_in[12];
    const float* b_out = (const float*)d_in[13];
    float* out = (float*)d_out;

    static int smem_set = 0;
    if (!smem_set) {
        cudaFuncSetAttribute(gemm2_kernel, cudaFuncAttributeMaxDynamicSharedMemorySize,
                             GEMM_SMEM);
        smem_set = 1;
    }

    dim3 wgrid(64, 6);
    prep_w_kernel<<<wgrid, 256>>>(Wl[0], Wr[0], Wl[1], Wr[1], Wl[2], Wr[2]);

    zero_kernel<<<(NN + 255) / 256, 256>>>();
    hist_kernel<<<(NE / 4 + 255) / 256, 256>>>(ei, batch);
    scan1_kernel<<<NB_SCAN, 1024>>>();
    scan2_kernel<<<1, 32>>>();
    scan3_kernel<<<NB_SCAN, 1024>>>();
    scatter_kernel<<<(NE / 4 + 255) / 256, 256>>>(ei);

    dim3 ggrid((NN + MT - 1) / MT, 2);
    for (int l = 0; l < 3; l++) {
        gemm2_kernel<<<ggrid, 256, GEMM_SMEM>>>(l, x);
        agg_kernel<<<(NN + 7) / 8, 256>>>(l, (l == 2) ? 1 : 0, bl[l], W_out, batch);
    }

    final_out_kernel<<<(NG + 255) / 256, 256>>>(out, b_out);
}